// round 10
// baseline (speedup 1.0000x reference)
#include <cuda_runtime.h>
#include <cuda_bf16.h>
#include <math.h>
#include <stdint.h>

#define S_LEN 2048
#define B_SZ  256
#define NIN   128
#define H_SZ  256
#define NOUT  128
#define CL    16

// g_Zx: [s][j][b] float; g_h: [s][b][j] float; g_hJB: [s][j][b] (fallback)
__device__ float g_Zx [134217728];
__device__ float g_h  [134217728];
__device__ float g_hJB[134217728];
__device__ unsigned int g_bar;

__device__ __forceinline__ float gelu_exact(float x){
    return 0.5f * x * (1.0f + erff(x * 0.70710678118654752440f));
}

__global__ void k_init(){ g_bar = 0u; }

// ---------------- PTX helpers (baseline ISA only) ----------------
__device__ __forceinline__ uint32_t smem_u32(const void* p){
    uint32_t a;
    asm("{ .reg .u64 t; cvta.to.shared.u64 t, %1; cvt.u32.u64 %0, t; }" : "=r"(a) : "l"(p));
    return a;
}
__device__ __forceinline__ uint32_t mapa_sh(uint32_t laddr, uint32_t rank){
    uint32_t r;
    asm("mapa.shared::cluster.u32 %0, %1, %2;" : "=r"(r) : "r"(laddr), "r"(rank));
    return r;
}
__device__ __forceinline__ void dsm_st_v2f(uint32_t raddr, float a, float b){
    asm volatile("st.shared::cluster.v2.f32 [%0], {%1,%2};" :: "r"(raddr), "f"(a), "f"(b) : "memory");
}
__device__ __forceinline__ void dsm_st_b64(uint32_t raddr, unsigned long long v){
    asm volatile("st.shared::cluster.b64 [%0], %1;" :: "r"(raddr), "l"(v) : "memory");
}
#define CLUSTER_SYNC() do { \
    asm volatile("barrier.cluster.arrive.aligned;" ::: "memory"); \
    asm volatile("barrier.cluster.wait.aligned;" ::: "memory"); } while(0)

#define LDSM4(r, a) \
    asm volatile("ldmatrix.sync.aligned.m8n8.x4.shared.b16 {%0,%1,%2,%3}, [%4];" \
        : "=r"((r)[0]), "=r"((r)[1]), "=r"((r)[2]), "=r"((r)[3]) : "r"(a))

#define MMA16816(d, a, b0r, b1r) \
    asm volatile("mma.sync.aligned.m16n8k16.row.col.f32.bf16.bf16.f32 " \
        "{%0,%1,%2,%3},{%4,%5,%6,%7},{%8,%9},{%0,%1,%2,%3};" \
        : "+f"((d)[0]), "+f"((d)[1]), "+f"((d)[2]), "+f"((d)[3]) \
        : "r"((a)[0]), "r"((a)[1]), "r"((a)[2]), "r"((a)[3]), "r"(b0r), "r"(b1r))

// ---------------- SMEM map (dynamic) ----------------
#define WROW     528
#define SM_WHI   0
#define SM_WLO   33792
#define SM_BHI   67584
#define SM_BLO   101376
#define SM_Z     135168
#define SM_PART  152320
#define SM_PART2 154368
#define SM_BNS   156416
#define SM_TOTAL 156928

// ---------------------------------------------------------------------------
// Kernel A: Zx[s][j][b] = b_ih[j] + sum_k X[b][s][k] W_ih[j][k]
// ---------------------------------------------------------------------------
__global__ __launch_bounds__(256) void k_zx(const float* __restrict__ X,
                                            const float* __restrict__ Wih,
                                            const float* __restrict__ bih){
    __shared__ float Xs[64][68];
    __shared__ float Ws[64][64];
    const int s  = blockIdx.x;
    const int j0 = blockIdx.y * 64;
    const int b0 = blockIdx.z * 64;
    const int tid = threadIdx.x;
    const int tx = tid & 15, ty = tid >> 4;

    float acc[4][4] = {};
    for (int kc = 0; kc < NIN; kc += 64){
        __syncthreads();
        for (int i = tid; i < 64*64; i += 256){
            int b = i >> 6, k = i & 63;
            Xs[k][b] = X[((size_t)(b0 + b) * S_LEN + s) * NIN + kc + k];
        }
        for (int i = tid; i < 64*64; i += 256){
            int j = i >> 6, k = i & 63;
            Ws[j][k] = Wih[(size_t)(j0 + j) * (NIN + H_SZ) + kc + k];
        }
        __syncthreads();
        #pragma unroll 8
        for (int k = 0; k < 64; ++k){
            float4 xv = *(const float4*)&Xs[k][tx*4];
            #pragma unroll
            for (int jj = 0; jj < 4; ++jj){
                float w = Ws[ty*4 + jj][k];
                acc[jj][0] += w * xv.x;  acc[jj][1] += w * xv.y;
                acc[jj][2] += w * xv.z;  acc[jj][3] += w * xv.w;
            }
        }
    }
    #pragma unroll
    for (int jj = 0; jj < 4; ++jj){
        int j = j0 + ty*4 + jj;
        float bb = bih[j];
        float4 o;
        o.x = acc[jj][0] + bb; o.y = acc[jj][1] + bb;
        o.z = acc[jj][2] + bb; o.w = acc[jj][3] + bb;
        *(float4*)&g_Zx[((size_t)s * H_SZ + j) * B_SZ + b0 + tx*4] = o;
    }
}

// ---------------------------------------------------------------------------
// Kernel B (primary): 16-CTA cluster spine, split-bf16 mma.sync
// ---------------------------------------------------------------------------
__global__ __launch_bounds__(256, 1)
void k_rec(const float* __restrict__ Wih,
           const float* __restrict__ gamma,
           const float* __restrict__ beta){
    extern __shared__ char smem[];
    const uint32_t smb = smem_u32(smem);
    const int tid = threadIdx.x;
    const int wid = tid >> 5, lane = tid & 31;
    uint32_t rank;
    asm("mov.u32 %0, %%cluster_ctarank;" : "=r"(rank));
    const int jq = rank & 3, bt = rank >> 2;
    const int j0 = jq * 64, b0 = bt * 64;
    const int mi = wid >> 2, ni = wid & 3;

    for (int i = tid; i < 64*256; i += 256){
        int r = i >> 8, c = i & 255;
        float w = Wih[(size_t)(j0 + r) * (NIN + H_SZ) + NIN + c];
        __nv_bfloat16 hi = __float2bfloat16_rn(w);
        __nv_bfloat16 lo = __float2bfloat16_rn(w - __bfloat162float(hi));
        *(__nv_bfloat16*)(smem + SM_WHI + r*WROW + c*2) = hi;
        *(__nv_bfloat16*)(smem + SM_WLO + r*WROW + c*2) = lo;
    }
    for (int i = tid; i < (64*WROW)/4; i += 256){
        ((uint32_t*)(smem + SM_BHI))[i] = 0u;
        ((uint32_t*)(smem + SM_BLO))[i] = 0u;
    }
    float gm = 1.f, bt_ = 0.f;
    if (tid < 64){ gm = gamma[j0 + tid]; bt_ = beta[j0 + tid]; }

    uint32_t rBhi[3], rBlo[3];
    {
        int n = 0;
        for (int q = 0; q < 4; ++q){
            if (q == jq) continue;
            uint32_t rr = (uint32_t)(4*bt + q);
            rBhi[n] = mapa_sh(smb + SM_BHI, rr);
            rBlo[n] = mapa_sh(smb + SM_BLO, rr);
            ++n;
        }
    }
    uint32_t rP2[4];
    for (int k = 0; k < 4; ++k) rP2[k] = mapa_sh(smb + SM_PART2, (uint32_t)(jq + 4*k));

    __syncthreads();
    CLUSTER_SYNC();

    const uint32_t arow = (lane & 7) + ((lane >> 3) & 1) * 8;
    const uint32_t acol = (lane >> 4);
    const uint32_t aHiB = smb + SM_WHI + (mi*32 + arow)*WROW + acol*16;
    const uint32_t aLoB = smb + SM_WLO + (mi*32 + arow)*WROW + acol*16;
    const uint32_t brow = (lane & 7) + (lane >> 4) * 8;
    const uint32_t bcol = (lane >> 3) & 1;
    const uint32_t bHiB = smb + SM_BHI + (ni*16 + brow)*WROW + bcol*16;
    const uint32_t bLoB = smb + SM_BLO + (ni*16 + brow)*WROW + bcol*16;

    float* Zf = (float*)(smem + SM_Z);
    float2* part  = (float2*)(smem + SM_PART);
    float2* part2 = (float2*)(smem + SM_PART2);
    float2* bns   = (float2*)(smem + SM_BNS);

    const int rA0 = mi*32 + (lane >> 2);
    const int cc0 = ni*16 + 2*(lane & 3);

    for (int s = 0; s < S_LEN; ++s){
        float2 zx[2][2][2];
        #pragma unroll
        for (int mf = 0; mf < 2; ++mf)
        #pragma unroll
        for (int nf = 0; nf < 2; ++nf){
            const float* zp = g_Zx + ((size_t)s*H_SZ + j0 + rA0 + mf*16)*B_SZ + b0 + cc0 + nf*8;
            zx[mf][nf][0] = __ldcs((const float2*)zp);
            zx[mf][nf][1] = __ldcs((const float2*)(zp + 8*B_SZ));
        }

        float acc[2][2][4] = {};
        #pragma unroll
        for (int kc = 0; kc < 16; ++kc){
            const uint32_t ko = kc * 32;
            uint32_t Ah0[4], Ah1[4], Al0[4], Al1[4], Bh[4], Bl[4];
            LDSM4(Ah0, aHiB + ko);
            LDSM4(Ah1, aHiB + 16*WROW + ko);
            LDSM4(Al0, aLoB + ko);
            LDSM4(Al1, aLoB + 16*WROW + ko);
            LDSM4(Bh, bHiB + ko);
            LDSM4(Bl, bLoB + ko);
            #pragma unroll
            for (int nf = 0; nf < 2; ++nf){
                MMA16816(acc[0][nf], Ah0, Bh[2*nf], Bh[2*nf+1]);
                MMA16816(acc[1][nf], Ah1, Bh[2*nf], Bh[2*nf+1]);
                MMA16816(acc[0][nf], Ah0, Bl[2*nf], Bl[2*nf+1]);
                MMA16816(acc[1][nf], Ah1, Bl[2*nf], Bl[2*nf+1]);
                MMA16816(acc[0][nf], Al0, Bh[2*nf], Bh[2*nf+1]);
                MMA16816(acc[1][nf], Al1, Bh[2*nf], Bh[2*nf+1]);
            }
        }

        #pragma unroll
        for (int mf = 0; mf < 2; ++mf)
        #pragma unroll
        for (int nf = 0; nf < 2; ++nf){
            acc[mf][nf][0] += zx[mf][nf][0].x;
            acc[mf][nf][1] += zx[mf][nf][0].y;
            acc[mf][nf][2] += zx[mf][nf][1].x;
            acc[mf][nf][3] += zx[mf][nf][1].y;
        }

        float r1[2][2], r2[2][2];
        #pragma unroll
        for (int mf = 0; mf < 2; ++mf){
            #pragma unroll
            for (int hf = 0; hf < 2; ++hf){
                float a = acc[mf][0][2*hf], b = acc[mf][0][2*hf+1];
                float c = acc[mf][1][2*hf], d = acc[mf][1][2*hf+1];
                r1[mf][hf] = a + b + c + d;
                r2[mf][hf] = a*a + b*b + c*c + d*d;
            }
        }
        #pragma unroll
        for (int mf = 0; mf < 2; ++mf)
        #pragma unroll
        for (int hf = 0; hf < 2; ++hf){
            r1[mf][hf] += __shfl_xor_sync(0xffffffffu, r1[mf][hf], 1);
            r1[mf][hf] += __shfl_xor_sync(0xffffffffu, r1[mf][hf], 2);
            r2[mf][hf] += __shfl_xor_sync(0xffffffffu, r2[mf][hf], 1);
            r2[mf][hf] += __shfl_xor_sync(0xffffffffu, r2[mf][hf], 2);
        }
        if ((lane & 3) == 0){
            int rr = lane >> 2;
            #pragma unroll
            for (int mf = 0; mf < 2; ++mf)
            #pragma unroll
            for (int hf = 0; hf < 2; ++hf){
                int row = mi*32 + mf*16 + rr + hf*8;
                part[ni*64 + row] = make_float2(r1[mf][hf], r2[mf][hf]);
            }
        }

        #pragma unroll
        for (int mf = 0; mf < 2; ++mf)
        #pragma unroll
        for (int nf = 0; nf < 2; ++nf){
            int rA = rA0 + mf*16;
            int cc = cc0 + nf*8;
            Zf[rA*67 + cc]     = acc[mf][nf][0];
            Zf[rA*67 + cc + 1] = acc[mf][nf][1];
            Zf[(rA+8)*67 + cc]     = acc[mf][nf][2];
            Zf[(rA+8)*67 + cc + 1] = acc[mf][nf][3];
        }
        __syncthreads();

        if (tid < 64){
            float S1 = 0.f, S2 = 0.f;
            #pragma unroll
            for (int n = 0; n < 4; ++n){
                float2 v = part[n*64 + tid];
                S1 += v.x; S2 += v.y;
            }
            uint32_t off = ((uint32_t)bt*64 + (uint32_t)tid) * 8;
            #pragma unroll
            for (int k = 0; k < 4; ++k) dsm_st_v2f(rP2[k] + off, S1, S2);
        }
        CLUSTER_SYNC();   // #1

        if (tid < 64){
            float T1 = 0.f, T2 = 0.f;
            #pragma unroll
            for (int k = 0; k < 4; ++k){
                float2 v = part2[k*64 + tid];
                T1 += v.x; T2 += v.y;
            }
            float mu  = T1 * (1.0f/256.0f);
            float var = T2 * (1.0f/256.0f) - mu*mu;
            float sc  = rsqrtf(var + 1e-5f) * gm;
            bns[tid] = make_float2(sc, bt_ - mu * sc);
        }
        __syncthreads();

        {
            const int b = tid & 63, jc = tid >> 6;
            float hv[16];
            unsigned long long hp[4], lp[4];
            #pragma unroll
            for (int q = 0; q < 4; ++q){
                unsigned long long h64 = 0ull, l64 = 0ull;
                #pragma unroll
                for (int i = 0; i < 4; ++i){
                    int j = jc*16 + q*4 + i;
                    float2 ss = bns[j];
                    float z = Zf[j*67 + b];
                    float h = gelu_exact(z * ss.x + ss.y);
                    hv[q*4 + i] = h;
                    __nv_bfloat16 hb = __float2bfloat16_rn(h);
                    __nv_bfloat16 lb = __float2bfloat16_rn(h - __bfloat162float(hb));
                    unsigned short hbits = *(unsigned short*)&hb;
                    unsigned short lbits = *(unsigned short*)&lb;
                    h64 |= (unsigned long long)hbits << (16*i);
                    l64 |= (unsigned long long)lbits << (16*i);
                }
                hp[q] = h64; lp[q] = l64;
            }
            float4* gh = (float4*)&g_h[((size_t)s*B_SZ + b0 + b)*H_SZ + j0 + jc*16];
            #pragma unroll
            for (int q = 0; q < 4; ++q)
                __stcs(gh + q, make_float4(hv[4*q], hv[4*q+1], hv[4*q+2], hv[4*q+3]));

            if (s + 1 < S_LEN){
                uint32_t off = (uint32_t)b*WROW + (uint32_t)(j0 + jc*16)*2;
                #pragma unroll
                for (int q = 0; q < 4; ++q){
                    *(unsigned long long*)(smem + SM_BHI + off + q*8) = hp[q];
                    *(unsigned long long*)(smem + SM_BLO + off + q*8) = lp[q];
                }
                #pragma unroll
                for (int r = 0; r < 3; ++r){
                    #pragma unroll
                    for (int q = 0; q < 4; ++q){
                        dsm_st_b64(rBhi[r] + off + q*8, hp[q]);
                        dsm_st_b64(rBlo[r] + off + q*8, lp[q]);
                    }
                }
            }
        }
        if (s + 1 < S_LEN) CLUSTER_SYNC();   // #2
    }
}

// ---------------------------------------------------------------------------
// Fallback spine (R1-proven): 64 CTAs, grid barrier, writes g_hJB [s][j][b]
// ---------------------------------------------------------------------------
__global__ __launch_bounds__(256) void k_rec_fb(const float* __restrict__ Wih,
                                                const float* __restrict__ gamma,
                                                const float* __restrict__ beta){
    __shared__ float Wsm[H_SZ * 4];
    __shared__ float redsm[8][8];
    __shared__ float bns[8];

    const int tid = threadIdx.x;
    const int j0  = blockIdx.x * 4;
    const int lane = tid & 31, warp = tid >> 5;

    for (int i = tid; i < H_SZ * 4; i += 256){
        int k = i >> 2, jj = i & 3;
        Wsm[i] = Wih[(size_t)(j0 + jj) * (NIN + H_SZ) + NIN + k];
    }
    __syncthreads();

    for (int s = 0; s < S_LEN; ++s){
        const float* zx = g_Zx + ((size_t)s * H_SZ + j0) * B_SZ + tid;
        float a0 = zx[0], a1 = zx[256], a2 = zx[512], a3 = zx[768];

        if (s > 0){
            const float* hp = g_hJB + (size_t)(s-1) * H_SZ * B_SZ + tid;
            #pragma unroll 16
            for (int k = 0; k < H_SZ; ++k){
                float hv = __ldcg(hp + k * B_SZ);
                float4 wv = *(const float4*)&Wsm[k*4];
                a0 += hv * wv.x; a1 += hv * wv.y;
                a2 += hv * wv.z; a3 += hv * wv.w;
            }
        }
        float s10=a0, s11=a1, s12=a2, s13=a3;
        float s20=a0*a0, s21=a1*a1, s22=a2*a2, s23=a3*a3;
        #pragma unroll
        for (int off = 16; off; off >>= 1){
            s10 += __shfl_down_sync(0xffffffffu, s10, off);
            s11 += __shfl_down_sync(0xffffffffu, s11, off);
            s12 += __shfl_down_sync(0xffffffffu, s12, off);
            s13 += __shfl_down_sync(0xffffffffu, s13, off);
            s20 += __shfl_down_sync(0xffffffffu, s20, off);
            s21 += __shfl_down_sync(0xffffffffu, s21, off);
            s22 += __shfl_down_sync(0xffffffffu, s22, off);
            s23 += __shfl_down_sync(0xffffffffu, s23, off);
        }
        if (lane == 0){
            redsm[warp][0]=s10; redsm[warp][1]=s11; redsm[warp][2]=s12; redsm[warp][3]=s13;
            redsm[warp][4]=s20; redsm[warp][5]=s21; redsm[warp][6]=s22; redsm[warp][7]=s23;
        }
        __syncthreads();
        if (tid < 4){
            float S1 = 0.f, S2 = 0.f;
            #pragma unroll
            for (int w = 0; w < 8; ++w){ S1 += redsm[w][tid]; S2 += redsm[w][4+tid]; }
            float mu  = S1 * (1.0f/256.0f);
            float var = S2 * (1.0f/256.0f) - mu*mu;
            float rs  = rsqrtf(var + 1e-5f);
            float sc  = rs * gamma[j0 + tid];
            bns[tid]     = sc;
            bns[4 + tid] = beta[j0 + tid] - mu * sc;
        }
        __syncthreads();

        float h0 = gelu_exact(a0*bns[0] + bns[4]);
        float h1 = gelu_exact(a1*bns[1] + bns[5]);
        float h2 = gelu_exact(a2*bns[2] + bns[6]);
        float h3 = gelu_exact(a3*bns[3] + bns[7]);

        float* hw = g_hJB + ((size_t)s * H_SZ + j0) * B_SZ + tid;
        __stcg(hw,       h0);
        __stcg(hw + 256, h1);
        __stcg(hw + 512, h2);
        __stcg(hw + 768, h3);

        __threadfence();
        __syncthreads();
        if (tid == 0){
            atomicAdd(&g_bar, 1u);
            unsigned target = 64u * (unsigned)(s + 1);
            volatile unsigned int* bp = &g_bar;
            while (*bp < target) { }
            __threadfence();
        }
        __syncthreads();
    }
}

// ---------------------------------------------------------------------------
// Kernel C (primary): reads g_h [s][b][j]
// ---------------------------------------------------------------------------
__global__ __launch_bounds__(256) void k_out(const float* __restrict__ Who,
                                             const float* __restrict__ bho,
                                             float* __restrict__ out){
    __shared__ float Hs[64][68];
    __shared__ float Ws[64][64];
    const int s  = blockIdx.x;
    const int o0 = blockIdx.y * 64;
    const int b0 = blockIdx.z * 64;
    const int tid = threadIdx.x;
    const int tx = tid & 15, ty = tid >> 4;

    float acc[4][4] = {};
    for (int kc = 0; kc < H_SZ; kc += 64){
        __syncthreads();
        #pragma unroll
        for (int p = 0; p < 4; ++p){
            int b  = tid & 63;
            int kg = p*4 + (tid >> 6);
            float4 v = *(const float4*)&g_h[((size_t)s*B_SZ + b0 + b)*H_SZ + kc + kg*4];
            Hs[kg*4 + 0][b] = v.x;
            Hs[kg*4 + 1][b] = v.y;
            Hs[kg*4 + 2][b] = v.z;
            Hs[kg*4 + 3][b] = v.w;
        }
        for (int i = tid; i < 64*64; i += 256){
            int o = i >> 6, k = i & 63;
            Ws[o][k] = Who[(size_t)(o0 + o) * H_SZ + kc + k];
        }
        __syncthreads();
        #pragma unroll 8
        for (int k = 0; k < 64; ++k){
            float4 hv = *(const float4*)&Hs[k][tx*4];
            #pragma unroll
            for (int jj = 0; jj < 4; ++jj){
                float w = Ws[ty*4 + jj][k];
                acc[jj][0] += w * hv.x;  acc[jj][1] += w * hv.y;
                acc[jj][2] += w * hv.z;  acc[jj][3] += w * hv.w;
            }
        }
    }
    float bb[4];
    #pragma unroll
    for (int jj = 0; jj < 4; ++jj) bb[jj] = bho[o0 + ty*4 + jj];
    #pragma unroll
    for (int ii = 0; ii < 4; ++ii){
        float4 r;
        r.x = gelu_exact(acc[0][ii] + bb[0]);
        r.y = gelu_exact(acc[1][ii] + bb[1]);
        r.z = gelu_exact(acc[2][ii] + bb[2]);
        r.w = gelu_exact(acc[3][ii] + bb[3]);
        size_t idx = ((size_t)(b0 + tx*4 + ii) * S_LEN + s) * NOUT + o0 + ty*4;
        *(float4*)&out[idx] = r;
    }
}

// ---------------------------------------------------------------------------
// Kernel C (fallback): reads g_hJB [s][j][b]
// ---------------------------------------------------------------------------
__global__ __launch_bounds__(256) void k_out_fb(const float* __restrict__ Who,
                                                const float* __restrict__ bho,
                                                float* __restrict__ out){
    __shared__ float Hs[64][68];
    __shared__ float Ws[64][64];
    const int s  = blockIdx.x;
    const int o0 = blockIdx.y * 64;
    const int b0 = blockIdx.z * 64;
    const int tid = threadIdx.x;
    const int tx = tid & 15, ty = tid >> 4;

    float acc[4][4] = {};
    for (int kc = 0; kc < H_SZ; kc += 64){
        __syncthreads();
        for (int i = tid; i < 64*64; i += 256){
            int k = i >> 6, b = i & 63;
            Hs[k][b] = g_hJB[((size_t)s * H_SZ + kc + k) * B_SZ + b0 + b];
        }
        for (int i = tid; i < 64*64; i += 256){
            int o = i >> 6, k = i & 63;
            Ws[o][k] = Who[(size_t)(o0 + o) * H_SZ + kc + k];
        }
        __syncthreads();
        #pragma unroll 8
        for (int k = 0; k < 64; ++k){
            float4 hv = *(const float4*)&Hs[k][tx*4];
            #pragma unroll
            for (int jj = 0; jj < 4; ++jj){
                float w = Ws[ty*4 + jj][k];
                acc[jj][0] += w * hv.x;  acc[jj][1] += w * hv.y;
                acc[jj][2] += w * hv.z;  acc[jj][3] += w * hv.w;
            }
        }
    }
    float bb[4];
    #pragma unroll
    for (int jj = 0; jj < 4; ++jj) bb[jj] = bho[o0 + ty*4 + jj];
    #pragma unroll
    for (int ii = 0; ii < 4; ++ii){
        float4 r;
        r.x = gelu_exact(acc[0][ii] + bb[0]);
        r.y = gelu_exact(acc[1][ii] + bb[1]);
        r.z = gelu_exact(acc[2][ii] + bb[2]);
        r.w = gelu_exact(acc[3][ii] + bb[3]);
        size_t idx = ((size_t)(b0 + tx*4 + ii) * S_LEN + s) * NOUT + o0 + ty*4;
        *(float4*)&out[idx] = r;
    }
}

// ---------------------------------------------------------------------------
extern "C" void kernel_launch(void* const* d_in, const int* in_sizes, int n_in,
                              void* d_out, int out_size) {
    const float* X     = (const float*)d_in[0];
    const float* Wih   = (const float*)d_in[1];
    const float* bih   = (const float*)d_in[2];
    const float* Who   = (const float*)d_in[3];
    const float* bho   = (const float*)d_in[4];
    const float* gamma = (const float*)d_in[5];
    const float* beta  = (const float*)d_in[6];
    float* out = (float*)d_out;

    cudaFuncSetAttribute(k_rec, cudaFuncAttributeMaxDynamicSharedMemorySize, SM_TOTAL);
    cudaFuncSetAttribute(k_rec, cudaFuncAttributeNonPortableClusterSizeAllowed, 1);

    // Capture-safe feasibility query (no stream work): can a 16-CTA cluster
    // of this kernel be placed at all?
    cudaLaunchConfig_t cfg = {};
    cfg.gridDim  = dim3(CL, 1, 1);
    cfg.blockDim = dim3(256, 1, 1);
    cfg.dynamicSmemBytes = SM_TOTAL;
    cfg.stream = 0;
    cudaLaunchAttribute at[1];
    at[0].id = cudaLaunchAttributeClusterDimension;
    at[0].val.clusterDim.x = CL;
    at[0].val.clusterDim.y = 1;
    at[0].val.clusterDim.z = 1;
    cfg.attrs = at;
    cfg.numAttrs = 1;

    int maxClusters = 0;
    cudaError_t qe = cudaOccupancyMaxActiveClusters(&maxClusters, k_rec, &cfg);
    bool use_cluster = (qe == cudaSuccess && maxClusters >= 1);
    cudaGetLastError();  // clear any sticky error from the query

    k_zx<<<dim3(S_LEN, H_SZ/64, B_SZ/64), 256>>>(X, Wih, bih);

    if (use_cluster){
        cudaLaunchKernelEx(&cfg, k_rec, Wih, gamma, beta);
        k_out<<<dim3(S_LEN, NOUT/64, B_SZ/64), 256>>>(Who, bho, out);
    } else {
        k_init<<<1, 1>>>();
        k_rec_fb<<<64, 256>>>(Wih, gamma, beta);
        k_out_fb<<<dim3(S_LEN, NOUT/64, B_SZ/64), 256>>>(Who, bho, out);
    }
}

// round 14
// speedup vs baseline: 2.2827x; 2.2827x over previous
#include <cuda_runtime.h>
#include <cuda_bf16.h>
#include <math.h>
#include <stdint.h>

#define S_LEN 2048
#define B_SZ  256
#define NIN   128
#define H_SZ  256
#define NOUT  128
#define NCTA  64

// g_Zx: [s][j][b] float; g_h: [s][b][j] float (consumed by k_out)
__device__ float g_Zx[134217728];
__device__ float g_h [134217728];
// per-step bf16 hi/lo h exchange buffers: [b 256][j 256]
__device__ __align__(16) unsigned short g_hb_hi[65536];
__device__ __align__(16) unsigned short g_hb_lo[65536];
// BN partials: [bt 8][j 256] float2
__device__ float2 g_part[2048];
__device__ unsigned int g_bar;

__device__ __forceinline__ float gelu_exact(float x){
    return 0.5f * x * (1.0f + erff(x * 0.70710678118654752440f));
}

__global__ void k_init(){ g_bar = 0u; }

__device__ __forceinline__ uint32_t smem_u32(const void* p){
    uint32_t a;
    asm("{ .reg .u64 t; cvta.to.shared.u64 t, %1; cvt.u32.u64 %0, t; }" : "=r"(a) : "l"(p));
    return a;
}

#define LDSM4(r, a) \
    asm volatile("ldmatrix.sync.aligned.m8n8.x4.shared.b16 {%0,%1,%2,%3}, [%4];" \
        : "=r"((r)[0]), "=r"((r)[1]), "=r"((r)[2]), "=r"((r)[3]) : "r"(a))

#define MMA16816(d, a, b0r, b1r) \
    asm volatile("mma.sync.aligned.m16n8k16.row.col.f32.bf16.bf16.f32 " \
        "{%0,%1,%2,%3},{%4,%5,%6,%7},{%8,%9},{%0,%1,%2,%3};" \
        : "+f"((d)[0]), "+f"((d)[1]), "+f"((d)[2]), "+f"((d)[3]) \
        : "r"((a)[0]), "r"((a)[1]), "r"((a)[2]), "r"((a)[3]), "r"(b0r), "r"(b1r))

// ---------------- SMEM map (dynamic) ----------------
#define WROW     528            // 256 bf16 + 16B pad: conflict-free ldmatrix
#define SM_WHI   0              // 32 x 528
#define SM_WLO   16896
#define SM_BHI   33792          // 32 b-rows x 528 (cols = j = K dim)
#define SM_BLO   50688
#define SM_Z     67584          // float Zf[32][33]
#define SM_PART  71808          // float2 [2][32]
#define SM_BNS   72320          // float2 [32]
#define SM_TOTAL 72576

// release/acquire grid barrier on monotonic counter
__device__ __forceinline__ void grid_bar(int tid, unsigned int target){
    __syncthreads();
    if (tid == 0){
        asm volatile("red.release.gpu.global.add.u32 [%0], 1;" :: "l"(&g_bar) : "memory");
        unsigned int v;
        do {
            asm volatile("ld.acquire.gpu.global.u32 %0, [%1];" : "=r"(v) : "l"(&g_bar) : "memory");
        } while (v < target);
    }
    __syncthreads();
}

// ---------------------------------------------------------------------------
// Kernel A: Zx[s][j][b] = b_ih[j] + sum_k X[b][s][k] W_ih[j][k]
// ---------------------------------------------------------------------------
__global__ __launch_bounds__(256) void k_zx(const float* __restrict__ X,
                                            const float* __restrict__ Wih,
                                            const float* __restrict__ bih){
    __shared__ float Xs[64][68];
    __shared__ float Ws[64][64];
    const int s  = blockIdx.x;
    const int j0 = blockIdx.y * 64;
    const int b0 = blockIdx.z * 64;
    const int tid = threadIdx.x;
    const int tx = tid & 15, ty = tid >> 4;

    float acc[4][4] = {};
    for (int kc = 0; kc < NIN; kc += 64){
        __syncthreads();
        for (int i = tid; i < 64*64; i += 256){
            int b = i >> 6, k = i & 63;
            Xs[k][b] = X[((size_t)(b0 + b) * S_LEN + s) * NIN + kc + k];
        }
        for (int i = tid; i < 64*64; i += 256){
            int j = i >> 6, k = i & 63;
            Ws[j][k] = Wih[(size_t)(j0 + j) * (NIN + H_SZ) + kc + k];
        }
        __syncthreads();
        #pragma unroll 8
        for (int k = 0; k < 64; ++k){
            float4 xv = *(const float4*)&Xs[k][tx*4];
            #pragma unroll
            for (int jj = 0; jj < 4; ++jj){
                float w = Ws[ty*4 + jj][k];
                acc[jj][0] += w * xv.x;  acc[jj][1] += w * xv.y;
                acc[jj][2] += w * xv.z;  acc[jj][3] += w * xv.w;
            }
        }
    }
    #pragma unroll
    for (int jj = 0; jj < 4; ++jj){
        int j = j0 + ty*4 + jj;
        float bb = bih[j];
        float4 o;
        o.x = acc[jj][0] + bb; o.y = acc[jj][1] + bb;
        o.z = acc[jj][2] + bb; o.w = acc[jj][3] + bb;
        *(float4*)&g_Zx[((size_t)s * H_SZ + j) * B_SZ + b0 + tx*4] = o;
    }
}

// ---------------------------------------------------------------------------
// Kernel B: 64-CTA grid-barrier spine, split-bf16 mma.sync, L2 exchange.
// CTA r: jq = r&7 (j group of 32), bt = r>>3 (b tile of 32). 128 threads.
// ---------------------------------------------------------------------------
__global__ __launch_bounds__(128, 1)
void k_rec(const float* __restrict__ Wih,
           const float* __restrict__ gamma,
           const float* __restrict__ beta){
    extern __shared__ char smem[];
    const uint32_t smb = smem_u32(smem);
    const int tid = threadIdx.x;
    const int wid = tid >> 5, lane = tid & 31;
    const int jq = blockIdx.x & 7, bt = blockIdx.x >> 3;
    const int j0 = jq * 32, b0 = bt * 32;
    const int mi = wid >> 1, ni = wid & 1;   // warp tile: 16j x 16b

    // ---- init: W hi/lo (32 rows x 256 k), zero B operands (h0 = 0) ----
    for (int i = tid; i < 32*256; i += 128){
        int r = i >> 8, c = i & 255;
        float w = Wih[(size_t)(j0 + r) * (NIN + H_SZ) + NIN + c];
        __nv_bfloat16 hi = __float2bfloat16_rn(w);
        __nv_bfloat16 lo = __float2bfloat16_rn(w - __bfloat162float(hi));
        *(__nv_bfloat16*)(smem + SM_WHI + r*WROW + c*2) = hi;
        *(__nv_bfloat16*)(smem + SM_WLO + r*WROW + c*2) = lo;
    }
    for (int i = tid; i < (2*32*WROW)/4; i += 128)
        ((uint32_t*)(smem + SM_BHI))[i] = 0u;
    float gm = 1.f, bt_ = 0.f;
    if (tid < 32){ gm = gamma[j0 + tid]; bt_ = beta[j0 + tid]; }
    __syncthreads();

    // ldmatrix per-lane bases (constant over steps)
    const uint32_t arow = (lane & 7) + ((lane >> 3) & 1) * 8;
    const uint32_t acol = (lane >> 4);
    const uint32_t aHiB = smb + SM_WHI + (mi*16 + arow)*WROW + acol*16;
    const uint32_t aLoB = smb + SM_WLO + (mi*16 + arow)*WROW + acol*16;
    const uint32_t brow = (lane & 7) + (lane >> 4) * 8;
    const uint32_t bcol = (lane >> 3) & 1;
    const uint32_t bHiB = smb + SM_BHI + (ni*16 + brow)*WROW + bcol*16;
    const uint32_t bLoB = smb + SM_BLO + (ni*16 + brow)*WROW + bcol*16;

    float*  Zf      = (float*)(smem + SM_Z);       // [32 j][33] (b cols)
    float2* part_sm = (float2*)(smem + SM_PART);   // [2 ni][32 j]
    float2* bns     = (float2*)(smem + SM_BNS);    // [32 j]

    const int rA0 = mi*16 + (lane >> 2);            // local j row (c0/c1)
    const int cc0 = ni*16 + 2*(lane & 3);           // local b col base

    for (int s = 0; s < S_LEN; ++s){
        // ---- Zx fragment prefetch (in flight during MMA) ----
        float2 zx[2][2];   // [nf][hf]
        #pragma unroll
        for (int nf = 0; nf < 2; ++nf)
        #pragma unroll
        for (int hf = 0; hf < 2; ++hf)
            zx[nf][hf] = __ldcs((const float2*)&g_Zx[
                ((size_t)s*H_SZ + j0 + rA0 + hf*8)*B_SZ + b0 + cc0 + nf*8]);

        // ---- MMA: 3-pass split bf16, K=256 ----
        float acc[2][4] = {};
        #pragma unroll
        for (int kc = 0; kc < 16; ++kc){
            const uint32_t ko = kc * 32;
            uint32_t Ah[4], Al[4], Bh[4], Bl[4];
            LDSM4(Ah, aHiB + ko);
            LDSM4(Al, aLoB + ko);
            LDSM4(Bh, bHiB + ko);
            LDSM4(Bl, bLoB + ko);
            #pragma unroll
            for (int nf = 0; nf < 2; ++nf){
                MMA16816(acc[nf], Ah, Bh[2*nf], Bh[2*nf+1]);
                MMA16816(acc[nf], Ah, Bl[2*nf], Bl[2*nf+1]);
                MMA16816(acc[nf], Al, Bh[2*nf], Bh[2*nf+1]);
            }
        }
        #pragma unroll
        for (int nf = 0; nf < 2; ++nf)
        #pragma unroll
        for (int hf = 0; hf < 2; ++hf){
            acc[nf][2*hf]   += zx[nf][hf].x;
            acc[nf][2*hf+1] += zx[nf][hf].y;
        }

        // ---- per-j partial sums over this warp's 16 b ----
        #pragma unroll
        for (int hf = 0; hf < 2; ++hf){
            float a = acc[0][2*hf], b = acc[0][2*hf+1];
            float c = acc[1][2*hf], d = acc[1][2*hf+1];
            float r1 = a + b + c + d;
            float r2 = a*a + b*b + c*c + d*d;
            r1 += __shfl_xor_sync(0xffffffffu, r1, 1);
            r1 += __shfl_xor_sync(0xffffffffu, r1, 2);
            r2 += __shfl_xor_sync(0xffffffffu, r2, 1);
            r2 += __shfl_xor_sync(0xffffffffu, r2, 2);
            if ((lane & 3) == 0)
                part_sm[ni*32 + mi*16 + (lane>>2) + hf*8] = make_float2(r1, r2);
        }

        // ---- stage z to SMEM for b-mapped gelu ----
        #pragma unroll
        for (int nf = 0; nf < 2; ++nf)
        #pragma unroll
        for (int hf = 0; hf < 2; ++hf){
            int j = rA0 + hf*8;
            int c = cc0 + nf*8;
            Zf[j*33 + c]     = acc[nf][2*hf];
            Zf[j*33 + c + 1] = acc[nf][2*hf+1];
        }
        __syncthreads();

        // ---- publish partials, barrier 1 ----
        if (tid < 32){
            float2 p0 = part_sm[tid], p1 = part_sm[32 + tid];
            float2 v = make_float2(p0.x + p1.x, p0.y + p1.y);
            __stcg(&g_part[bt*H_SZ + j0 + tid], v);
        }
        grid_bar(tid, (unsigned)NCTA * (unsigned)(2*s + 1));

        // ---- BN coefficients ----
        if (tid < 32){
            float T1 = 0.f, T2 = 0.f;
            #pragma unroll
            for (int t = 0; t < 8; ++t){
                float2 v = __ldcg(&g_part[t*H_SZ + j0 + tid]);
                T1 += v.x; T2 += v.y;
            }
            float mu  = T1 * (1.0f/256.0f);
            float var = T2 * (1.0f/256.0f) - mu*mu;
            float sc  = rsqrtf(var + 1e-5f) * gm;
            bns[tid] = make_float2(sc, bt_ - mu * sc);
        }
        __syncthreads();

        // ---- gelu + h writeback (thread: b = tid&31, jc = tid>>5 -> 8 j) ----
        {
            const int b = tid & 31, jc = tid >> 5;
            float hv[8];
            uint32_t hi4[4], lo4[4];
            #pragma unroll
            for (int i = 0; i < 8; ++i){
                int j = jc*8 + i;
                float2 ss = bns[j];
                hv[i] = gelu_exact(Zf[j*33 + b] * ss.x + ss.y);
            }
            #pragma unroll
            for (int p = 0; p < 4; ++p){
                __nv_bfloat16 h0 = __float2bfloat16_rn(hv[2*p]);
                __nv_bfloat16 h1 = __float2bfloat16_rn(hv[2*p+1]);
                __nv_bfloat16 l0 = __float2bfloat16_rn(hv[2*p]   - __bfloat162float(h0));
                __nv_bfloat16 l1 = __float2bfloat16_rn(hv[2*p+1] - __bfloat162float(h1));
                hi4[p] = (uint32_t)*(unsigned short*)&h0 | ((uint32_t)*(unsigned short*)&h1 << 16);
                lo4[p] = (uint32_t)*(unsigned short*)&l0 | ((uint32_t)*(unsigned short*)&l1 << 16);
            }
            int col = j0 + jc*8;
            __stcg((uint4*)&g_hb_hi[(b0 + b)*H_SZ + col],
                   make_uint4(hi4[0], hi4[1], hi4[2], hi4[3]));
            __stcg((uint4*)&g_hb_lo[(b0 + b)*H_SZ + col],
                   make_uint4(lo4[0], lo4[1], lo4[2], lo4[3]));
            float* gh = &g_h[((size_t)s*B_SZ + b0 + b)*H_SZ + col];
            __stcs((float4*)gh,       make_float4(hv[0], hv[1], hv[2], hv[3]));
            __stcs((float4*)(gh + 4), make_float4(hv[4], hv[5], hv[6], hv[7]));
        }

        // ---- barrier 2: all h(s) visible; then load next-step B operands ----
        grid_bar(tid, (unsigned)NCTA * (unsigned)(2*s + 2));

        if (s + 1 < S_LEN){
            #pragma unroll
            for (int it = 0; it < 8; ++it){
                int idx = tid + it*128;          // 0..1023
                int row = idx >> 5, c = idx & 31;
                uint4 v = __ldcg((const uint4*)&g_hb_hi[(b0 + row)*H_SZ + c*8]);
                *(uint4*)(smem + SM_BHI + row*WROW + c*16) = v;
                uint4 w = __ldcg((const uint4*)&g_hb_lo[(b0 + row)*H_SZ + c*8]);
                *(uint4*)(smem + SM_BLO + row*WROW + c*16) = w;
            }
            __syncthreads();
        }
    }
}

// ---------------------------------------------------------------------------
// Kernel C: out[b][s][o] = gelu(sum_k h[s][b][k] W_ho[o][k] + b_ho[o])
// ---------------------------------------------------------------------------
__global__ __launch_bounds__(256) void k_out(const float* __restrict__ Who,
                                             const float* __restrict__ bho,
                                             float* __restrict__ out){
    __shared__ float Hs[64][68];
    __shared__ float Ws[64][64];
    const int s  = blockIdx.x;
    const int o0 = blockIdx.y * 64;
    const int b0 = blockIdx.z * 64;
    const int tid = threadIdx.x;
    const int tx = tid & 15, ty = tid >> 4;

    float acc[4][4] = {};
    for (int kc = 0; kc < H_SZ; kc += 64){
        __syncthreads();
        #pragma unroll
        for (int p = 0; p < 4; ++p){
            int b  = tid & 63;
            int kg = p*4 + (tid >> 6);
            float4 v = *(const float4*)&g_h[((size_t)s*B_SZ + b0 + b)*H_SZ + kc + kg*4];
            Hs[kg*4 + 0][b] = v.x;
            Hs[kg*4 + 1][b] = v.y;
            Hs[kg*4 + 2][b] = v.z;
            Hs[kg*4 + 3][b] = v.w;
        }
        for (int i = tid; i < 64*64; i += 256){
            int o = i >> 6, k = i & 63;
            Ws[o][k] = Who[(size_t)(o0 + o) * H_SZ + kc + k];
        }
        __syncthreads();
        #pragma unroll 8
        for (int k = 0; k < 64; ++k){
            float4 hv = *(const float4*)&Hs[k][tx*4];
            #pragma unroll
            for (int jj = 0; jj < 4; ++jj){
                float w = Ws[ty*4 + jj][k];
                acc[jj][0] += w * hv.x;  acc[jj][1] += w * hv.y;
                acc[jj][2] += w * hv.z;  acc[jj][3] += w * hv.w;
            }
        }
    }
    float bb[4];
    #pragma unroll
    for (int jj = 0; jj < 4; ++jj) bb[jj] = bho[o0 + ty*4 + jj];
    #pragma unroll
    for (int ii = 0; ii < 4; ++ii){
        float4 r;
        r.x = gelu_exact(acc[0][ii] + bb[0]);
        r.y = gelu_exact(acc[1][ii] + bb[1]);
        r.z = gelu_exact(acc[2][ii] + bb[2]);
        r.w = gelu_exact(acc[3][ii] + bb[3]);
        size_t idx = ((size_t)(b0 + tx*4 + ii) * S_LEN + s) * NOUT + o0 + ty*4;
        *(float4*)&out[idx] = r;
    }
}

// ---------------------------------------------------------------------------
extern "C" void kernel_launch(void* const* d_in, const int* in_sizes, int n_in,
                              void* d_out, int out_size) {
    const float* X     = (const float*)d_in[0];
    const float* Wih   = (const float*)d_in[1];
    const float* bih   = (const float*)d_in[2];
    const float* Who   = (const float*)d_in[3];
    const float* bho   = (const float*)d_in[4];
    const float* gamma = (const float*)d_in[5];
    const float* beta  = (const float*)d_in[6];
    float* out = (float*)d_out;

    cudaFuncSetAttribute(k_rec, cudaFuncAttributeMaxDynamicSharedMemorySize, SM_TOTAL);

    k_init<<<1, 1>>>();
    k_zx <<<dim3(S_LEN, H_SZ/64, B_SZ/64), 256>>>(X, Wih, bih);
    k_rec<<<NCTA, 128, SM_TOTAL>>>(Wih, gamma, beta);
    k_out<<<dim3(S_LEN, NOUT/64, B_SZ/64), 256>>>(Who, bho, out);
}

// round 15
// speedup vs baseline: 2.4020x; 1.0522x over previous
#include <cuda_runtime.h>
#include <cuda_bf16.h>
#include <math.h>
#include <stdint.h>

#define S_LEN 2048
#define B_SZ  256
#define NIN   128
#define H_SZ  256
#define NOUT  128
#define NCTA  128

// g_Zx: [s][j][b] float; g_h: [s][b][j] float (consumed by k_out)
__device__ float g_Zx[134217728];
__device__ float g_h [134217728];
// per-step bf16 hi/lo h exchange buffers: [b 256][j 256]
__device__ __align__(16) unsigned short g_hb_hi[65536];
__device__ __align__(16) unsigned short g_hb_lo[65536];
// BN partials: [bt 8][j 256] float2
__device__ float2 g_part[2048];
__device__ unsigned int g_bar;

__device__ __forceinline__ float gelu_exact(float x){
    return 0.5f * x * (1.0f + erff(x * 0.70710678118654752440f));
}

__global__ void k_init(){ g_bar = 0u; }

__device__ __forceinline__ uint32_t smem_u32(const void* p){
    uint32_t a;
    asm("{ .reg .u64 t; cvta.to.shared.u64 t, %1; cvt.u32.u64 %0, t; }" : "=r"(a) : "l"(p));
    return a;
}

#define LDSM4(r, a) \
    asm volatile("ldmatrix.sync.aligned.m8n8.x4.shared.b16 {%0,%1,%2,%3}, [%4];" \
        : "=r"((r)[0]), "=r"((r)[1]), "=r"((r)[2]), "=r"((r)[3]) : "r"(a))

#define LDSM2(r, a) \
    asm volatile("ldmatrix.sync.aligned.m8n8.x2.shared.b16 {%0,%1}, [%2];" \
        : "=r"((r)[0]), "=r"((r)[1]) : "r"(a))

#define MMA16816(d, a, b0r, b1r) \
    asm volatile("mma.sync.aligned.m16n8k16.row.col.f32.bf16.bf16.f32 " \
        "{%0,%1,%2,%3},{%4,%5,%6,%7},{%8,%9},{%0,%1,%2,%3};" \
        : "+f"((d)[0]), "+f"((d)[1]), "+f"((d)[2]), "+f"((d)[3]) \
        : "r"((a)[0]), "r"((a)[1]), "r"((a)[2]), "r"((a)[3]), "r"(b0r), "r"(b1r))

// ---------------- SMEM map (dynamic) ----------------
#define WROW     528            // 256 bf16 + 16B pad: conflict-free ldmatrix
#define SM_WHI   0              // 16 j-rows x 528
#define SM_WLO   8448
#define SM_BHI   16896          // 32 b-rows x 528 (cols = j = K dim)
#define SM_BLO   33792
#define SM_Z     50688          // float Zf[16][33]
#define SM_PART  52800          // float2 [4 warp][16 j]
#define SM_BNS   53312          // float2 [16]
#define SM_TOTAL 53504

// release/acquire grid barrier on monotonic counter
__device__ __forceinline__ void grid_bar(int tid, unsigned int target){
    __syncthreads();
    if (tid == 0){
        asm volatile("red.release.gpu.global.add.u32 [%0], 1;" :: "l"(&g_bar) : "memory");
        unsigned int v;
        do {
            asm volatile("ld.acquire.gpu.global.u32 %0, [%1];" : "=r"(v) : "l"(&g_bar) : "memory");
        } while (v < target);
    }
    __syncthreads();
}

// ---------------------------------------------------------------------------
// Kernel A: Zx[s][j][b] = b_ih[j] + sum_k X[b][s][k] W_ih[j][k]
// ---------------------------------------------------------------------------
__global__ __launch_bounds__(256) void k_zx(const float* __restrict__ X,
                                            const float* __restrict__ Wih,
                                            const float* __restrict__ bih){
    __shared__ float Xs[64][68];
    __shared__ float Ws[64][64];
    const int s  = blockIdx.x;
    const int j0 = blockIdx.y * 64;
    const int b0 = blockIdx.z * 64;
    const int tid = threadIdx.x;
    const int tx = tid & 15, ty = tid >> 4;

    float acc[4][4] = {};
    for (int kc = 0; kc < NIN; kc += 64){
        __syncthreads();
        for (int i = tid; i < 64*64; i += 256){
            int b = i >> 6, k = i & 63;
            Xs[k][b] = X[((size_t)(b0 + b) * S_LEN + s) * NIN + kc + k];
        }
        for (int i = tid; i < 64*64; i += 256){
            int j = i >> 6, k = i & 63;
            Ws[j][k] = Wih[(size_t)(j0 + j) * (NIN + H_SZ) + kc + k];
        }
        __syncthreads();
        #pragma unroll 8
        for (int k = 0; k < 64; ++k){
            float4 xv = *(const float4*)&Xs[k][tx*4];
            #pragma unroll
            for (int jj = 0; jj < 4; ++jj){
                float w = Ws[ty*4 + jj][k];
                acc[jj][0] += w * xv.x;  acc[jj][1] += w * xv.y;
                acc[jj][2] += w * xv.z;  acc[jj][3] += w * xv.w;
            }
        }
    }
    #pragma unroll
    for (int jj = 0; jj < 4; ++jj){
        int j = j0 + ty*4 + jj;
        float bb = bih[j];
        float4 o;
        o.x = acc[jj][0] + bb; o.y = acc[jj][1] + bb;
        o.z = acc[jj][2] + bb; o.w = acc[jj][3] + bb;
        *(float4*)&g_Zx[((size_t)s * H_SZ + j) * B_SZ + b0 + tx*4] = o;
    }
}

// ---------------------------------------------------------------------------
// Kernel B: 128-CTA grid-barrier spine, split-bf16 mma.sync, L2 exchange.
// CTA r: jq = r&15 (16 j rows), bt = r>>4 (32 b cols). 128 threads, 4 warps.
// Warp w: n-subtile w*8 (16j x 8b), 48 HMMA/step.
// ---------------------------------------------------------------------------
__global__ __launch_bounds__(128, 1)
void k_rec(const float* __restrict__ Wih,
           const float* __restrict__ gamma,
           const float* __restrict__ beta){
    extern __shared__ char smem[];
    const uint32_t smb = smem_u32(smem);
    const int tid = threadIdx.x;
    const int wid = tid >> 5, lane = tid & 31;
    const int jq = blockIdx.x & 15, bt = blockIdx.x >> 4;
    const int j0 = jq * 16, b0 = bt * 32;
    const int n_off = wid * 8;               // warp's b-octet

    // ---- init: W hi/lo (16 rows x 256 k), zero B operands (h0 = 0) ----
    for (int i = tid; i < 16*256; i += 128){
        int r = i >> 8, c = i & 255;
        float w = Wih[(size_t)(j0 + r) * (NIN + H_SZ) + NIN + c];
        __nv_bfloat16 hi = __float2bfloat16_rn(w);
        __nv_bfloat16 lo = __float2bfloat16_rn(w - __bfloat162float(hi));
        *(__nv_bfloat16*)(smem + SM_WHI + r*WROW + c*2) = hi;
        *(__nv_bfloat16*)(smem + SM_WLO + r*WROW + c*2) = lo;
    }
    for (int i = tid; i < (2*32*WROW)/4; i += 128)
        ((uint32_t*)(smem + SM_BHI))[i] = 0u;
    float gm = 1.f, bt_ = 0.f;
    if (tid < 16){ gm = gamma[j0 + tid]; bt_ = beta[j0 + tid]; }
    __syncthreads();

    // ldmatrix per-lane bases (constant over steps)
    const uint32_t arow = (lane & 7) + ((lane >> 3) & 1) * 8;
    const uint32_t acol = (lane >> 4);
    const uint32_t aHiB = smb + SM_WHI + arow*WROW + acol*16;
    const uint32_t aLoB = smb + SM_WLO + arow*WROW + acol*16;
    // x2 B fragment: lanes 0-15 give addresses (row = n_off + (lane&7), k-half = (lane>>3)&1)
    const uint32_t bHiB = smb + SM_BHI + (n_off + (lane & 7))*WROW + ((lane >> 3) & 1)*16;
    const uint32_t bLoB = smb + SM_BLO + (n_off + (lane & 7))*WROW + ((lane >> 3) & 1)*16;

    float*  Zf      = (float*)(smem + SM_Z);       // [16 j][33] (b cols)
    float2* part_sm = (float2*)(smem + SM_PART);   // [4 warp][16 j]
    float2* bns     = (float2*)(smem + SM_BNS);    // [16 j]

    const int rA0 = lane >> 2;                     // local j row (c0/c1)
    const int cc0 = n_off + 2*(lane & 3);          // local b col base

    for (int s = 0; s < S_LEN; ++s){
        // ---- Zx fragment prefetch (in flight during MMA) ----
        float2 zx[2];   // [hf]
        #pragma unroll
        for (int hf = 0; hf < 2; ++hf)
            zx[hf] = __ldcs((const float2*)&g_Zx[
                ((size_t)s*H_SZ + j0 + rA0 + hf*8)*B_SZ + b0 + cc0]);

        // ---- MMA: 3-pass split bf16, K=256, 48 HMMA/warp ----
        float acc[4] = {};
        #pragma unroll
        for (int kc = 0; kc < 16; ++kc){
            const uint32_t ko = kc * 32;
            uint32_t Ah[4], Al[4], Bh[2], Bl[2];
            LDSM4(Ah, aHiB + ko);
            LDSM4(Al, aLoB + ko);
            LDSM2(Bh, bHiB + ko);
            LDSM2(Bl, bLoB + ko);
            MMA16816(acc, Ah, Bh[0], Bh[1]);
            MMA16816(acc, Ah, Bl[0], Bl[1]);
            MMA16816(acc, Al, Bh[0], Bh[1]);
        }
        #pragma unroll
        for (int hf = 0; hf < 2; ++hf){
            acc[2*hf]   += zx[hf].x;
            acc[2*hf+1] += zx[hf].y;
        }

        // ---- per-j partial sums over this warp's 8 b ----
        #pragma unroll
        for (int hf = 0; hf < 2; ++hf){
            float r1 = acc[2*hf] + acc[2*hf+1];
            float r2 = acc[2*hf]*acc[2*hf] + acc[2*hf+1]*acc[2*hf+1];
            r1 += __shfl_xor_sync(0xffffffffu, r1, 1);
            r1 += __shfl_xor_sync(0xffffffffu, r1, 2);
            r2 += __shfl_xor_sync(0xffffffffu, r2, 1);
            r2 += __shfl_xor_sync(0xffffffffu, r2, 2);
            if ((lane & 3) == 0)
                part_sm[wid*16 + rA0 + hf*8] = make_float2(r1, r2);
        }

        // ---- stage z to SMEM for b-mapped gelu ----
        #pragma unroll
        for (int hf = 0; hf < 2; ++hf){
            int j = rA0 + hf*8;
            Zf[j*33 + cc0]     = acc[2*hf];
            Zf[j*33 + cc0 + 1] = acc[2*hf+1];
        }
        __syncthreads();

        // ---- publish partials, barrier 1 ----
        if (tid < 16){
            float T1 = 0.f, T2 = 0.f;
            #pragma unroll
            for (int w = 0; w < 4; ++w){
                float2 v = part_sm[w*16 + tid];
                T1 += v.x; T2 += v.y;
            }
            __stcg(&g_part[bt*H_SZ + j0 + tid], make_float2(T1, T2));
        }
        grid_bar(tid, (unsigned)NCTA * (unsigned)(2*s + 1));

        // ---- BN coefficients ----
        if (tid < 16){
            float T1 = 0.f, T2 = 0.f;
            #pragma unroll
            for (int t = 0; t < 8; ++t){
                float2 v = __ldcg(&g_part[t*H_SZ + j0 + tid]);
                T1 += v.x; T2 += v.y;
            }
            float mu  = T1 * (1.0f/256.0f);
            float var = T2 * (1.0f/256.0f) - mu*mu;
            float sc  = rsqrtf(var + 1e-5f) * gm;
            bns[tid] = make_float2(sc, bt_ - mu * sc);
        }
        __syncthreads();

        // ---- gelu + h writeback (thread: b = tid&31, jc = tid>>5 -> 4 j) ----
        {
            const int b = tid & 31, jc = tid >> 5;
            float hv[4];
            uint32_t hi2[2], lo2[2];
            #pragma unroll
            for (int i = 0; i < 4; ++i){
                int j = jc*4 + i;
                float2 ss = bns[j];
                hv[i] = gelu_exact(Zf[j*33 + b] * ss.x + ss.y);
            }
            #pragma unroll
            for (int p = 0; p < 2; ++p){
                __nv_bfloat16 h0 = __float2bfloat16_rn(hv[2*p]);
                __nv_bfloat16 h1 = __float2bfloat16_rn(hv[2*p+1]);
                __nv_bfloat16 l0 = __float2bfloat16_rn(hv[2*p]   - __bfloat162float(h0));
                __nv_bfloat16 l1 = __float2bfloat16_rn(hv[2*p+1] - __bfloat162float(h1));
                hi2[p] = (uint32_t)*(unsigned short*)&h0 | ((uint32_t)*(unsigned short*)&h1 << 16);
                lo2[p] = (uint32_t)*(unsigned short*)&l0 | ((uint32_t)*(unsigned short*)&l1 << 16);
            }
            int col = j0 + jc*4;
            __stcg((uint2*)&g_hb_hi[(b0 + b)*H_SZ + col], make_uint2(hi2[0], hi2[1]));
            __stcg((uint2*)&g_hb_lo[(b0 + b)*H_SZ + col], make_uint2(lo2[0], lo2[1]));
            __stcs((float4*)&g_h[((size_t)s*B_SZ + b0 + b)*H_SZ + col],
                   make_float4(hv[0], hv[1], hv[2], hv[3]));
        }

        // ---- barrier 2: all h(s) visible; then load next-step B operands ----
        grid_bar(tid, (unsigned)NCTA * (unsigned)(2*s + 2));

        if (s + 1 < S_LEN){
            #pragma unroll
            for (int it = 0; it < 8; ++it){
                int idx = tid + it*128;          // 0..1023
                int row = idx >> 5, c = idx & 31;
                uint4 v = __ldcg((const uint4*)&g_hb_hi[(b0 + row)*H_SZ + c*8]);
                *(uint4*)(smem + SM_BHI + row*WROW + c*16) = v;
                uint4 w = __ldcg((const uint4*)&g_hb_lo[(b0 + row)*H_SZ + c*8]);
                *(uint4*)(smem + SM_BLO + row*WROW + c*16) = w;
            }
            __syncthreads();
        }
    }
}

// ---------------------------------------------------------------------------
// Kernel C: out[b][s][o] = gelu(sum_k h[s][b][k] W_ho[o][k] + b_ho[o])
// ---------------------------------------------------------------------------
__global__ __launch_bounds__(256) void k_out(const float* __restrict__ Who,
                                             const float* __restrict__ bho,
                                             float* __restrict__ out){
    __shared__ float Hs[64][68];
    __shared__ float Ws[64][64];
    const int s  = blockIdx.x;
    const int o0 = blockIdx.y * 64;
    const int b0 = blockIdx.z * 64;
    const int tid = threadIdx.x;
    const int tx = tid & 15, ty = tid >> 4;

    float acc[4][4] = {};
    for (int kc = 0; kc < H_SZ; kc += 64){
        __syncthreads();
        #pragma unroll
        for (int p = 0; p < 4; ++p){
            int b  = tid & 63;
            int kg = p*4 + (tid >> 6);
            float4 v = *(const float4*)&g_h[((size_t)s*B_SZ + b0 + b)*H_SZ + kc + kg*4];
            Hs[kg*4 + 0][b] = v.x;
            Hs[kg*4 + 1][b] = v.y;
            Hs[kg*4 + 2][b] = v.z;
            Hs[kg*4 + 3][b] = v.w;
        }
        for (int i = tid; i < 64*64; i += 256){
            int o = i >> 6, k = i & 63;
            Ws[o][k] = Who[(size_t)(o0 + o) * H_SZ + kc + k];
        }
        __syncthreads();
        #pragma unroll 8
        for (int k = 0; k < 64; ++k){
            float4 hv = *(const float4*)&Hs[k][tx*4];
            #pragma unroll
            for (int jj = 0; jj < 4; ++jj){
                float w = Ws[ty*4 + jj][k];
                acc[jj][0] += w * hv.x;  acc[jj][1] += w * hv.y;
                acc[jj][2] += w * hv.z;  acc[jj][3] += w * hv.w;
            }
        }
    }
    float bb[4];
    #pragma unroll
    for (int jj = 0; jj < 4; ++jj) bb[jj] = bho[o0 + ty*4 + jj];
    #pragma unroll
    for (int ii = 0; ii < 4; ++ii){
        float4 r;
        r.x = gelu_exact(acc[0][ii] + bb[0]);
        r.y = gelu_exact(acc[1][ii] + bb[1]);
        r.z = gelu_exact(acc[2][ii] + bb[2]);
        r.w = gelu_exact(acc[3][ii] + bb[3]);
        size_t idx = ((size_t)(b0 + tx*4 + ii) * S_LEN + s) * NOUT + o0 + ty*4;
        *(float4*)&out[idx] = r;
    }
}

// ---------------------------------------------------------------------------
extern "C" void kernel_launch(void* const* d_in, const int* in_sizes, int n_in,
                              void* d_out, int out_size) {
    const float* X     = (const float*)d_in[0];
    const float* Wih   = (const float*)d_in[1];
    const float* bih   = (const float*)d_in[2];
    const float* Who   = (const float*)d_in[3];
    const float* bho   = (const float*)d_in[4];
    const float* gamma = (const float*)d_in[5];
    const float* beta  = (const float*)d_in[6];
    float* out = (float*)d_out;

    cudaFuncSetAttribute(k_rec, cudaFuncAttributeMaxDynamicSharedMemorySize, SM_TOTAL);

    k_init<<<1, 1>>>();
    k_zx <<<dim3(S_LEN, H_SZ/64, B_SZ/64), 256>>>(X, Wih, bih);
    k_rec<<<NCTA, 128, SM_TOTAL>>>(Wih, gamma, beta);
    k_out<<<dim3(S_LEN, NOUT/64, B_SZ/64), 256>>>(Who, bho, out);
}